// round 6
// baseline (speedup 1.0000x reference)
#include <cuda_runtime.h>
#include <cuda_fp16.h>
#include <stdint.h>

// Problem constants (this instance):
//   NUM_EMB=200000, DIM=64, UPDATE_COUNT=2, HASHED_SIZE=3,200,000
//   NUM_BAGS=16384, BAG_LEN=50, TOTAL=819200
// Inputs: x(int32), offsets(int32), hashed_weight(f32), weight_idx(int32)
// Output: float32 [NUM_BAGS, DIM]
//
// FLOOR NOTE: total L1tex wavefronts ~30M (25.6M random 4B gathers in K1 +
// 3.3M 128B row reads in K2) / 148 SM ~= 106us @1.9GHz. Kernel is at this
// floor; only wavefront-count reductions can beat it.

#define UPDATE_COUNT 2
#define EMB_CAPACITY (200000 * 64)

// Combined table in fp16: emb[e*64+d] = (half)(hw[widx[0,e,d]] + hw[widx[1,e,d]])
__device__ __half g_emb_h[EMB_CAPACITY];

// ---------------------------------------------------------------------------
// Kernel 1: build combined table. AT THE L1TEX WAVEFRONT FLOOR (25.6M random
// 4B gathers ~= 1 wf each ~= 91us) — frozen. widx .cs (streaming; keep hot hw
// resident in L2), hw .cg (skip L1).
// ---------------------------------------------------------------------------
__global__ void __launch_bounds__(256) build_emb_kernel(
    const int4* __restrict__ widx,
    const float* __restrict__ hw,
    int n8,                       // emb_elems / 8
    int stride4)                  // emb_elems / 4 (u-stride in int4 units)
{
    int i = blockIdx.x * blockDim.x + threadIdx.x;
    if (i >= n8) return;

    int4 a0 = __ldcs(&widx[2 * i]);
    int4 a1 = __ldcs(&widx[2 * i + 1]);
    int4 b0 = __ldcs(&widx[2 * i + stride4]);
    int4 b1 = __ldcs(&widx[2 * i + 1 + stride4]);

    float f0 = __ldcg(&hw[a0.x]) + __ldcg(&hw[b0.x]);
    float f1 = __ldcg(&hw[a0.y]) + __ldcg(&hw[b0.y]);
    float f2 = __ldcg(&hw[a0.z]) + __ldcg(&hw[b0.z]);
    float f3 = __ldcg(&hw[a0.w]) + __ldcg(&hw[b0.w]);
    float f4 = __ldcg(&hw[a1.x]) + __ldcg(&hw[b1.x]);
    float f5 = __ldcg(&hw[a1.y]) + __ldcg(&hw[b1.y]);
    float f6 = __ldcg(&hw[a1.z]) + __ldcg(&hw[b1.z]);
    float f7 = __ldcg(&hw[a1.w]) + __ldcg(&hw[b1.w]);

    __half2 h0 = __floats2half2_rn(f0, f1);
    __half2 h1 = __floats2half2_rn(f2, f3);
    __half2 h2 = __floats2half2_rn(f4, f5);
    __half2 h3 = __floats2half2_rn(f6, f7);

    uint4 o;
    o.x = *reinterpret_cast<uint32_t*>(&h0);
    o.y = *reinterpret_cast<uint32_t*>(&h1);
    o.z = *reinterpret_cast<uint32_t*>(&h2);
    o.w = *reinterpret_cast<uint32_t*>(&h3);
    reinterpret_cast<uint4*>(g_emb_h)[i] = o;
}

// ---------------------------------------------------------------------------
// Kernel 2: embedding bag. Warp-per-bag; fp16 rows are 128B -> one warp
// LDG.128 covers FOUR token rows (lane groups of 8). 16-token unroll keeps
// 4 independent LDG.128 in flight per lane (covers DRAM refill latency of the
// cold emb table). TWO half2 accumulator sets halve fp16 chain length
// (precision) at zero loop cost. fp32 fold + 256B coalesced store.
// ---------------------------------------------------------------------------
__global__ void __launch_bounds__(256) bag_sum_kernel(
    const int* __restrict__ x,
    const int* __restrict__ offsets,
    float* __restrict__ out,
    int num_bags, int total)
{
    const int BPB = 8;                      // bags (warps) per block
    __shared__ int sh[BPB][64];

    int w    = threadIdx.x >> 5;
    int lane = threadIdx.x & 31;
    int bag  = blockIdx.x * BPB + w;
    if (bag >= num_bags) return;

    int start = __ldg(&offsets[bag]);
    int end   = (bag + 1 < num_bags) ? __ldg(&offsets[bag + 1]) : total;
    int len   = end - start;

    for (int t = lane; t < len; t += 32)
        sh[w][t] = __ldg(&x[start + t]);
    __syncwarp();

    const uint4* __restrict__ emb16 = reinterpret_cast<const uint4*>(g_emb_h);
    int g = lane >> 3;                      // token group 0..3
    int q = lane & 7;                       // 16B chunk within 128B row

    __half2 z = __float2half2_rn(0.f);
    __half2 pA0 = z, pA1 = z, pA2 = z, pA3 = z;   // set A
    __half2 pB0 = z, pB1 = z, pB2 = z, pB3 = z;   // set B

    int t = 0;
    // 16 tokens per iteration: 4 independent LDG.128 in flight per lane
    for (; t + 16 <= len; t += 16) {
        uint4 va = __ldg(&emb16[(unsigned)sh[w][t +  0 + g] * 8 + q]);
        uint4 vb = __ldg(&emb16[(unsigned)sh[w][t +  4 + g] * 8 + q]);
        uint4 vc = __ldg(&emb16[(unsigned)sh[w][t +  8 + g] * 8 + q]);
        uint4 vd = __ldg(&emb16[(unsigned)sh[w][t + 12 + g] * 8 + q]);
        pA0 = __hadd2(pA0, *reinterpret_cast<const __half2*>(&va.x));
        pA1 = __hadd2(pA1, *reinterpret_cast<const __half2*>(&va.y));
        pA2 = __hadd2(pA2, *reinterpret_cast<const __half2*>(&va.z));
        pA3 = __hadd2(pA3, *reinterpret_cast<const __half2*>(&va.w));
        pB0 = __hadd2(pB0, *reinterpret_cast<const __half2*>(&vb.x));
        pB1 = __hadd2(pB1, *reinterpret_cast<const __half2*>(&vb.y));
        pB2 = __hadd2(pB2, *reinterpret_cast<const __half2*>(&vb.z));
        pB3 = __hadd2(pB3, *reinterpret_cast<const __half2*>(&vb.w));
        pA0 = __hadd2(pA0, *reinterpret_cast<const __half2*>(&vc.x));
        pA1 = __hadd2(pA1, *reinterpret_cast<const __half2*>(&vc.y));
        pA2 = __hadd2(pA2, *reinterpret_cast<const __half2*>(&vc.z));
        pA3 = __hadd2(pA3, *reinterpret_cast<const __half2*>(&vc.w));
        pB0 = __hadd2(pB0, *reinterpret_cast<const __half2*>(&vd.x));
        pB1 = __hadd2(pB1, *reinterpret_cast<const __half2*>(&vd.y));
        pB2 = __hadd2(pB2, *reinterpret_cast<const __half2*>(&vd.z));
        pB3 = __hadd2(pB3, *reinterpret_cast<const __half2*>(&vd.w));
    }
    for (; t + 4 <= len; t += 4) {
        uint4 v = __ldg(&emb16[(unsigned)sh[w][t + g] * 8 + q]);
        pA0 = __hadd2(pA0, *reinterpret_cast<const __half2*>(&v.x));
        pA1 = __hadd2(pA1, *reinterpret_cast<const __half2*>(&v.y));
        pA2 = __hadd2(pA2, *reinterpret_cast<const __half2*>(&v.z));
        pA3 = __hadd2(pA3, *reinterpret_cast<const __half2*>(&v.w));
    }
    if (t + g < len) {                      // tail: 1-3 tokens
        uint4 v = __ldg(&emb16[(unsigned)sh[w][t + g] * 8 + q]);
        pB0 = __hadd2(pB0, *reinterpret_cast<const __half2*>(&v.x));
        pB1 = __hadd2(pB1, *reinterpret_cast<const __half2*>(&v.y));
        pB2 = __hadd2(pB2, *reinterpret_cast<const __half2*>(&v.z));
        pB3 = __hadd2(pB3, *reinterpret_cast<const __half2*>(&v.w));
    }

    // Combine the two half2 sets in fp32, then fold the 4 token groups
    float2 fA, fB;
    fA = __half22float2(pA0); fB = __half22float2(pB0);
    float2 a0 = {fA.x + fB.x, fA.y + fB.y};
    fA = __half22float2(pA1); fB = __half22float2(pB1);
    float2 a1 = {fA.x + fB.x, fA.y + fB.y};
    fA = __half22float2(pA2); fB = __half22float2(pB2);
    float2 a2 = {fA.x + fB.x, fA.y + fB.y};
    fA = __half22float2(pA3); fB = __half22float2(pB3);
    float2 a3 = {fA.x + fB.x, fA.y + fB.y};

    #pragma unroll
    for (int off = 16; off >= 8; off >>= 1) {
        a0.x += __shfl_xor_sync(0xffffffffu, a0.x, off);
        a0.y += __shfl_xor_sync(0xffffffffu, a0.y, off);
        a1.x += __shfl_xor_sync(0xffffffffu, a1.x, off);
        a1.y += __shfl_xor_sync(0xffffffffu, a1.y, off);
        a2.x += __shfl_xor_sync(0xffffffffu, a2.x, off);
        a2.y += __shfl_xor_sync(0xffffffffu, a2.y, off);
        a3.x += __shfl_xor_sync(0xffffffffu, a3.x, off);
        a3.y += __shfl_xor_sync(0xffffffffu, a3.y, off);
    }

    if (lane < 8) {                         // 8 lanes x 32B = 256B coalesced
        float4 lo = make_float4(a0.x, a0.y, a1.x, a1.y);
        float4 hi = make_float4(a2.x, a2.y, a3.x, a3.y);
        float4* o = reinterpret_cast<float4*>(out) + (unsigned)bag * 16 + q * 2;
        o[0] = lo;
        o[1] = hi;
    }
}

// ---------------------------------------------------------------------------
extern "C" void kernel_launch(void* const* d_in, const int* in_sizes, int n_in,
                              void* d_out, int out_size)
{
    const int*   x       = (const int*)  d_in[0];
    const int*   offsets = (const int*)  d_in[1];
    const float* hw      = (const float*)d_in[2];
    const int*   widx    = (const int*)  d_in[3];

    int total     = in_sizes[0];
    int num_bags  = in_sizes[1];
    int wid_sz    = in_sizes[3];
    int emb_elems = wid_sz / UPDATE_COUNT;

    int n8 = emb_elems / 8;
    int threads1 = 256;
    int blocks1  = (n8 + threads1 - 1) / threads1;
    build_emb_kernel<<<blocks1, threads1>>>(
        (const int4*)widx, hw, n8, emb_elems / 4);

    int blocks2 = (num_bags + 7) / 8;
    bag_sum_kernel<<<blocks2, 256>>>(x, offsets, (float*)d_out, num_bags, total);
}

// round 7
// speedup vs baseline: 1.0021x; 1.0021x over previous
#include <cuda_runtime.h>
#include <cuda_fp16.h>
#include <stdint.h>

// Problem constants (this instance):
//   NUM_EMB=200000, DIM=64, UPDATE_COUNT=2, HASHED_SIZE=3,200,000
//   NUM_BAGS=16384, BAG_LEN=50, TOTAL=819200
// Inputs: x(int32), offsets(int32), hashed_weight(f32), weight_idx(int32)
// Output: float32 [NUM_BAGS, DIM]
//
// FLOOR NOTE: total L1tex wavefronts ~30M (25.6M random 4B gathers in K1 +
// 3.3M 128B row reads in K2) / 148 SM ~= 106us @1.9GHz. Kernel is at this
// floor. R6 lesson: MLP>2 per lane in K2 triggers cross-CTA L1tex-queue
// spread (B300 spr_max model) and REGRESSES — keep the 8-token loop.

#define UPDATE_COUNT 2
#define EMB_CAPACITY (200000 * 64)

// Combined table in fp16: emb[e*64+d] = (half)(hw[widx[0,e,d]] + hw[widx[1,e,d]])
__device__ __half g_emb_h[EMB_CAPACITY];

// ---------------------------------------------------------------------------
// Kernel 1: build combined table. AT THE L1TEX WAVEFRONT FLOOR (25.6M random
// 4B gathers ~= 1 wf each ~= 91us) — frozen. widx .cs (streaming; keep hot hw
// resident in L2), hw .cg (skip L1).
// ---------------------------------------------------------------------------
__global__ void __launch_bounds__(256) build_emb_kernel(
    const int4* __restrict__ widx,
    const float* __restrict__ hw,
    int n8,                       // emb_elems / 8
    int stride4)                  // emb_elems / 4 (u-stride in int4 units)
{
    int i = blockIdx.x * blockDim.x + threadIdx.x;
    if (i >= n8) return;

    int4 a0 = __ldcs(&widx[2 * i]);
    int4 a1 = __ldcs(&widx[2 * i + 1]);
    int4 b0 = __ldcs(&widx[2 * i + stride4]);
    int4 b1 = __ldcs(&widx[2 * i + 1 + stride4]);

    float f0 = __ldcg(&hw[a0.x]) + __ldcg(&hw[b0.x]);
    float f1 = __ldcg(&hw[a0.y]) + __ldcg(&hw[b0.y]);
    float f2 = __ldcg(&hw[a0.z]) + __ldcg(&hw[b0.z]);
    float f3 = __ldcg(&hw[a0.w]) + __ldcg(&hw[b0.w]);
    float f4 = __ldcg(&hw[a1.x]) + __ldcg(&hw[b1.x]);
    float f5 = __ldcg(&hw[a1.y]) + __ldcg(&hw[b1.y]);
    float f6 = __ldcg(&hw[a1.z]) + __ldcg(&hw[b1.z]);
    float f7 = __ldcg(&hw[a1.w]) + __ldcg(&hw[b1.w]);

    __half2 h0 = __floats2half2_rn(f0, f1);
    __half2 h1 = __floats2half2_rn(f2, f3);
    __half2 h2 = __floats2half2_rn(f4, f5);
    __half2 h3 = __floats2half2_rn(f6, f7);

    uint4 o;
    o.x = *reinterpret_cast<uint32_t*>(&h0);
    o.y = *reinterpret_cast<uint32_t*>(&h1);
    o.z = *reinterpret_cast<uint32_t*>(&h2);
    o.w = *reinterpret_cast<uint32_t*>(&h3);
    reinterpret_cast<uint4*>(g_emb_h)[i] = o;
}

// ---------------------------------------------------------------------------
// Kernel 2: embedding bag. Warp-per-bag; fp16 rows are 128B -> one warp
// LDG.128 covers FOUR token rows (lane groups of 8). 8-token loop = MLP 2
// per lane (R6: deeper MLP regresses via L1tex-queue spread). Dual half2
// accumulator sets (va->A, vb->B) halve the fp16 chain length at identical
// instruction count. emb loads .cg (zero reuse; skip L1). fp32 fold +
// 256B coalesced store.
// ---------------------------------------------------------------------------
__global__ void __launch_bounds__(256) bag_sum_kernel(
    const int* __restrict__ x,
    const int* __restrict__ offsets,
    float* __restrict__ out,
    int num_bags, int total)
{
    const int BPB = 8;                      // bags (warps) per block
    __shared__ int sh[BPB][64];

    int w    = threadIdx.x >> 5;
    int lane = threadIdx.x & 31;
    int bag  = blockIdx.x * BPB + w;
    if (bag >= num_bags) return;

    int start = __ldg(&offsets[bag]);
    int end   = (bag + 1 < num_bags) ? __ldg(&offsets[bag + 1]) : total;
    int len   = end - start;

    for (int t = lane; t < len; t += 32)
        sh[w][t] = __ldg(&x[start + t]);
    __syncwarp();

    const uint4* __restrict__ emb16 = reinterpret_cast<const uint4*>(g_emb_h);
    int g = lane >> 3;                      // token group 0..3
    int q = lane & 7;                       // 16B chunk within 128B row

    __half2 z = __float2half2_rn(0.f);
    __half2 pA0 = z, pA1 = z, pA2 = z, pA3 = z;   // set A
    __half2 pB0 = z, pB1 = z, pB2 = z, pB3 = z;   // set B

    int t = 0;
    // 8 tokens per iteration: 2 independent LDG.128 in flight per lane
    for (; t + 8 <= len; t += 8) {
        uint4 va = __ldcg(&emb16[(unsigned)sh[w][t + 0 + g] * 8 + q]);
        uint4 vb = __ldcg(&emb16[(unsigned)sh[w][t + 4 + g] * 8 + q]);
        pA0 = __hadd2(pA0, *reinterpret_cast<const __half2*>(&va.x));
        pA1 = __hadd2(pA1, *reinterpret_cast<const __half2*>(&va.y));
        pA2 = __hadd2(pA2, *reinterpret_cast<const __half2*>(&va.z));
        pA3 = __hadd2(pA3, *reinterpret_cast<const __half2*>(&va.w));
        pB0 = __hadd2(pB0, *reinterpret_cast<const __half2*>(&vb.x));
        pB1 = __hadd2(pB1, *reinterpret_cast<const __half2*>(&vb.y));
        pB2 = __hadd2(pB2, *reinterpret_cast<const __half2*>(&vb.z));
        pB3 = __hadd2(pB3, *reinterpret_cast<const __half2*>(&vb.w));
    }
    for (; t + 4 <= len; t += 4) {
        uint4 v = __ldcg(&emb16[(unsigned)sh[w][t + g] * 8 + q]);
        pA0 = __hadd2(pA0, *reinterpret_cast<const __half2*>(&v.x));
        pA1 = __hadd2(pA1, *reinterpret_cast<const __half2*>(&v.y));
        pA2 = __hadd2(pA2, *reinterpret_cast<const __half2*>(&v.z));
        pA3 = __hadd2(pA3, *reinterpret_cast<const __half2*>(&v.w));
    }
    if (t + g < len) {                      // tail: 1-3 tokens
        uint4 v = __ldcg(&emb16[(unsigned)sh[w][t + g] * 8 + q]);
        pB0 = __hadd2(pB0, *reinterpret_cast<const __half2*>(&v.x));
        pB1 = __hadd2(pB1, *reinterpret_cast<const __half2*>(&v.y));
        pB2 = __hadd2(pB2, *reinterpret_cast<const __half2*>(&v.z));
        pB3 = __hadd2(pB3, *reinterpret_cast<const __half2*>(&v.w));
    }

    // Combine the two half2 sets in fp32, then fold the 4 token groups
    float2 fA, fB;
    fA = __half22float2(pA0); fB = __half22float2(pB0);
    float2 a0 = {fA.x + fB.x, fA.y + fB.y};
    fA = __half22float2(pA1); fB = __half22float2(pB1);
    float2 a1 = {fA.x + fB.x, fA.y + fB.y};
    fA = __half22float2(pA2); fB = __half22float2(pB2);
    float2 a2 = {fA.x + fB.x, fA.y + fB.y};
    fA = __half22float2(pA3); fB = __half22float2(pB3);
    float2 a3 = {fA.x + fB.x, fA.y + fB.y};

    #pragma unroll
    for (int off = 16; off >= 8; off >>= 1) {
        a0.x += __shfl_xor_sync(0xffffffffu, a0.x, off);
        a0.y += __shfl_xor_sync(0xffffffffu, a0.y, off);
        a1.x += __shfl_xor_sync(0xffffffffu, a1.x, off);
        a1.y += __shfl_xor_sync(0xffffffffu, a1.y, off);
        a2.x += __shfl_xor_sync(0xffffffffu, a2.x, off);
        a2.y += __shfl_xor_sync(0xffffffffu, a2.y, off);
        a3.x += __shfl_xor_sync(0xffffffffu, a3.x, off);
        a3.y += __shfl_xor_sync(0xffffffffu, a3.y, off);
    }

    if (lane < 8) {                         // 8 lanes x 32B = 256B coalesced
        float4 lo = make_float4(a0.x, a0.y, a1.x, a1.y);
        float4 hi = make_float4(a2.x, a2.y, a3.x, a3.y);
        float4* o = reinterpret_cast<float4*>(out) + (unsigned)bag * 16 + q * 2;
        o[0] = lo;
        o[1] = hi;
    }
}

// ---------------------------------------------------------------------------
extern "C" void kernel_launch(void* const* d_in, const int* in_sizes, int n_in,
                              void* d_out, int out_size)
{
    const int*   x       = (const int*)  d_in[0];
    const int*   offsets = (const int*)  d_in[1];
    const float* hw      = (const float*)d_in[2];
    const int*   widx    = (const int*)  d_in[3];

    int total     = in_sizes[0];
    int num_bags  = in_sizes[1];
    int wid_sz    = in_sizes[3];
    int emb_elems = wid_sz / UPDATE_COUNT;

    int n8 = emb_elems / 8;
    int threads1 = 256;
    int blocks1  = (n8 + threads1 - 1) / threads1;
    build_emb_kernel<<<blocks1, threads1>>>(
        (const int4*)widx, hw, n8, emb_elems / 4);

    int blocks2 = (num_bags + 7) / 8;
    bag_sum_kernel<<<blocks2, 256>>>(x, offsets, (float*)d_out, num_bags, total);
}